// round 9
// baseline (speedup 1.0000x reference)
#include <cuda_runtime.h>

// ---------------------------------------------------------------------------
// B=1024, D=16384, K=8, NEG_RATIO=6 -> 48 negatives/row, SAMPLE_SEED=42
// JAX partitionable threefry (verified exact: rel_err=0.0 in R1/R4)
// ---------------------------------------------------------------------------
#define BB      1024
#define DD      16384
#define NTOT    (BB * DD)
#define NNEG    48
#define T       256
#define CH      8
#define ELEMS_PER_BLK (T * CH)            // 2048
#define NB1     (NTOT / ELEMS_PER_BLK)    // 8192 (8 blocks per row)
#define BLK_PER_ROW (DD / ELEMS_PER_BLK)  // 8
#define BCAP    64                        // per-block candidate cap (mean 16, sd 4)
#define CAP     512                       // per-row candidate cap (mean ~128)
#define THRESH  0xFE000000u               // P(candidate) = 1/128

__device__ unsigned long long g_cand[NB1 * BCAP];  // per-block candidate lists
__device__ int    g_bcnt[NB1];                     // per-block counts (bit30 = overflow)
__device__ float  g_part1[NB1];                    // per-block positive-term partials
__device__ double g_accd;                          // global loss accumulator
__device__ int    g_done;                          // k2 completion counter

// ---------------------------------------------------------------------------
// threefry2x32, key=(0,42), counter=(0,f).
// 10 of 20 rotations routed through mul.wide.u32 (FMA pipe) + 3-input LOP3
// to unload the ALU pipe (SHF). Adds left plain: ptxas alternates IMAD/IADD3.
// ---------------------------------------------------------------------------
__device__ __forceinline__ unsigned rot_s(unsigned v, int r) {     // ALU: SHF
    return __funnelshift_l(v, v, r);
}
__device__ __forceinline__ unsigned rot_m_xor(unsigned v, unsigned mul,
                                              unsigned x0) {       // FMA: IMAD.WIDE
    unsigned long long p = (unsigned long long)v * mul;   // lo = v<<r, hi = v>>(32-r)
    unsigned lo = (unsigned)p, hi = (unsigned)(p >> 32);
    unsigned res;                                         // (lo|hi)^x0 in one LOP3
    asm("lop3.b32 %0, %1, %2, %3, 0x56;" : "=r"(res) : "r"(lo), "r"(hi), "r"(x0));
    return res;
}

#define RS(r) { x0 += x1; x1 = rot_s(x1, (r)) ^ x0; }
#define RM(r) { x0 += x1; x1 = rot_m_xor(x1, 1u << (r), x0); }

__device__ __forceinline__ unsigned noise_bits(unsigned f) {
    const unsigned K1 = 42u;
    const unsigned K2 = 42u ^ 0x1BD11BDAu;
    unsigned x0 = 0u;
    unsigned x1 = f + K1;
    RM(13) RS(15) RM(26) RS(6)
    x0 += K1;  x1 += K2 + 1u;
    RM(17) RS(29) RM(16) RS(24)
    x0 += K2;  x1 += 2u;
    RM(13) RS(15) RM(26) RS(6)
    /* x0 += 0 */ x1 += K1 + 3u;
    RM(17) RS(29) RM(16) RS(24)
    x0 += K1;  x1 += K2 + 4u;
    RM(13) RS(15) RM(26) RS(6)
    x0 += K2;  x1 += 5u;
    return x0 ^ x1;            // partitionable scheme: out = o0 ^ o1
}
#undef RS
#undef RM

__device__ __forceinline__ float softplus_f(float x) {
    return fmaxf(x, 0.f) + log1pf(__expf(-fabsf(x)));
}

__device__ __forceinline__ unsigned long long pack_cand(unsigned bits, unsigned jloc) {
    return (((unsigned long long)(bits >> 9)) << 14)
         | (unsigned long long)(DD - 1u - jloc);      // minor key: lower j wins ties
}

// ---------------------------------------------------------------------------
// Kernel 1: threefry generation + positive-term loss + candidate compaction.
// One block = 2048 contiguous elements (1/8 of a row). Block 0 also resets
// the global accumulator state for this replay (stream order: k1 before k2).
// ---------------------------------------------------------------------------
__global__ void __launch_bounds__(T)
k1_gen(const float* __restrict__ pred, const float* __restrict__ target) {
    __shared__ unsigned long long s_buf[BCAP];
    __shared__ float warpbuf[T / 32];
    __shared__ int s_cnt;

    const int tid = threadIdx.x;
    const unsigned gbase = blockIdx.x * (unsigned)ELEMS_PER_BLK + (unsigned)tid * CH;
    const unsigned jloc0 = gbase & (DD - 1u);

    if (tid == 0) {
        s_cnt = 0;
        if (blockIdx.x == 0) { g_accd = 0.0; g_done = 0; }
    }
    __syncthreads();

    float t[CH];
    *reinterpret_cast<float4*>(&t[0]) =
        *reinterpret_cast<const float4*>(target + gbase);
    *reinterpret_cast<float4*>(&t[4]) =
        *reinterpret_cast<const float4*>(target + gbase + 4);

    // straight-line: 8 independent threefry chains (compiler interleaves)
    unsigned b[CH];
#pragma unroll
    for (int q = 0; q < CH; q++) b[q] = noise_bits(gbase + (unsigned)q);

    float acc = 0.f;
#pragma unroll
    for (int q = 0; q < CH; q++) {
        if (t[q] > 0.f) {                                   // rare (8/16384)
            acc += softplus_f(-pred[gbase + (unsigned)q]);  // positive BCE term
        } else if (b[q] >= THRESH) {                        // rare (1/128)
            int p = atomicAdd(&s_cnt, 1);
            if (p < BCAP) s_buf[p] = pack_cand(b[q], jloc0 + (unsigned)q);
        }
    }

    // block reduction of positive-term partial
    for (int off = 16; off; off >>= 1)
        acc += __shfl_down_sync(0xFFFFFFFFu, acc, off);
    if ((tid & 31) == 0) warpbuf[tid >> 5] = acc;
    __syncthreads();

    const int cnt = s_cnt;
    const int n = min(cnt, BCAP);
    if (tid < n)
        g_cand[blockIdx.x * BCAP + tid] = s_buf[tid];
    if (tid == 0) {
        g_bcnt[blockIdx.x] = (cnt > BCAP) ? (n | (1 << 30)) : n;
        float s = 0.f;
        for (int w = 0; w < T / 32; w++) s += warpbuf[w];
        g_part1[blockIdx.x] = s;
    }
}

// ---------------------------------------------------------------------------
// Kernel 2: per-row exact top-48 among candidates (unique composite keys ->
// exact JAX top_k semantics incl. lower-index tie-break), row total added to
// a global double accumulator; last block converts to out[0].
// ---------------------------------------------------------------------------
__global__ void __launch_bounds__(T)
k2_select(const float* __restrict__ pred, const float* __restrict__ target,
          float* __restrict__ out) {
    __shared__ unsigned long long cand[CAP];
    __shared__ float sel[NNEG];
    __shared__ float posbuf[BLK_PER_ROW];
    __shared__ int s_bc[BLK_PER_ROW];
    __shared__ int hist[256];
    __shared__ int s_C, s_cb, s_cc;

    const int row = blockIdx.x;
    const int tid = threadIdx.x;
    const unsigned rowbase = (unsigned)row * DD;
    const float* __restrict__ prow = pred + rowbase;
    const float* __restrict__ trow = target + rowbase;

    if (tid < BLK_PER_ROW) {
        s_bc[tid]   = g_bcnt[row * BLK_PER_ROW + tid];
        posbuf[tid] = g_part1[row * BLK_PER_ROW + tid];
    }
    __syncthreads();

    bool bad = false;
    int offs[BLK_PER_ROW];
    {
        int a = 0;
#pragma unroll
        for (int i = 0; i < BLK_PER_ROW; i++) {
            int c = s_bc[i];
            if (c & (1 << 30)) bad = true;
            c &= 0xFFFF;
            offs[i] = a;
            a += c;
        }
        if (tid == 0) s_C = a;
    }
    __syncthreads();
    int C = s_C;
    if (C < NNEG || C > CAP) bad = true;

    if (!bad) {
        // gather the 8 sub-lists into smem
#pragma unroll
        for (int i = 0; i < BLK_PER_ROW; i++) {
            const int c = s_bc[i] & 0xFFFF;
            for (int k2i = tid; k2i < c; k2i += T)
                cand[offs[i] + k2i] =
                    g_cand[(row * BLK_PER_ROW + i) * BCAP + k2i];
        }
        __syncthreads();
    } else {
        // ---- exact fallback (never taken: noise field is fixed) ----
        for (int i = tid; i < 256; i += T) hist[i] = 0;
        if (tid == 0) s_cc = 0;
        __syncthreads();
        for (int j = tid; j < DD; j += T) {
            if (trow[j] > 0.f) continue;
            atomicAdd(&hist[noise_bits(rowbase + j) >> 24], 1);
        }
        __syncthreads();
        if (tid == 0) {
            int a = 0, cb = 0;
            for (int bkt = 255; bkt >= 0; bkt--) {
                a += hist[bkt];
                if (a >= NNEG) { cb = bkt; break; }
            }
            s_cb = cb;
        }
        __syncthreads();
        const unsigned cb = (unsigned)s_cb;
        for (int j = tid; j < DD; j += T) {
            if (trow[j] > 0.f) continue;
            const unsigned bits = noise_bits(rowbase + j);
            if ((bits >> 24) >= cb) {
                int p = atomicAdd(&s_cc, 1);
                if (p < CAP) cand[p] = pack_cand(bits, (unsigned)j);
            }
        }
        __syncthreads();
        C = min(s_cc, CAP);
    }

    // ---- exact rank among C candidates (keys unique: value major, index minor)
    for (int i = tid; i < C; i += T) {
        const unsigned long long e = cand[i];
        int rank = 0;
        for (int u = 0; u < C; u++) rank += (cand[u] > e) ? 1 : 0;
        if (rank < NNEG) {
            const unsigned j = DD - 1u - (unsigned)(e & 0x3FFFULL);
            sel[rank] = softplus_f(prow[j]);
        }
    }
    __syncthreads();

    if (tid == 0) {
        float s = 0.f;
#pragma unroll
        for (int i = 0; i < NNEG; i++) s += sel[i];          // fixed order
#pragma unroll
        for (int i = 0; i < BLK_PER_ROW; i++) s += posbuf[i];
        atomicAdd(&g_accd, (double)s);
        __threadfence();
        int old = atomicAdd(&g_done, 1);
        if (old == BB - 1) {
            double v = *((volatile double*)&g_accd);
            out[0] = (float)v;
        }
    }
}

extern "C" void kernel_launch(void* const* d_in, const int* in_sizes, int n_in,
                              void* d_out, int out_size) {
    const float* pred   = (const float*)d_in[0];
    const float* target = (const float*)d_in[1];
    (void)in_sizes; (void)n_in; (void)out_size;

    k1_gen<<<NB1, T>>>(pred, target);
    k2_select<<<BB, T>>>(pred, target, (float*)d_out);
}